// round 4
// baseline (speedup 1.0000x reference)
#include <cuda_runtime.h>
#include <cuda_bf16.h>

// Problem constants (fixed by reference setup_inputs)
#define N_NODES 50000
#define CIN 64
#define COUT 64
#define E_MAX 800000

// -------- __device__ scratch (no allocations allowed) --------
__device__ float d_GW[N_NODES * COUT];    // G @ W^T            (12.8 MB)
__device__ float d_RWb[N_NODES * COUT];   // RSC @ W^T - b      (12.8 MB)
__device__ int   d_deg[N_NODES + 1];      // per-dst degree; [N_NODES] = region allocator
__device__ int   d_cursor[N_NODES];       // scatter cursors (region start, then end)
__device__ int   d_esrc[E_MAX];           // src node id per edge, grouped by dst

// packed dual-fp32 FMA (sm_103a f32x2 pipe; ptxas never auto-fuses this)
#define FMA2(d, a, bb, c) \
    asm("fma.rn.f32x2 %0, %1, %2, %3;" : "=l"(d) : "l"(a), "l"(bb), "l"(c))

// =====================================================================
// K1: fused GEMM: rows [0,N) -> GW = G @ W^T ; rows [N,2N) -> RWb = RSC @ W^T - b
// 256-row x 64-col tile, 128 threads, 16 rows x 8 cols per thread,
// inner product via fma.rn.f32x2 (rows packed in pairs, W duplicated in smem).
// =====================================================================
#define GT_STRIDE 260                      // 256 rows + 4 pad floats (16B-aligned rows)
#define SMEM_K1_BYTES ((64 * GT_STRIDE + 64 * 64 * 2) * 4)   // 99328

__global__ __launch_bounds__(128, 1) void k1_gemm(const float* __restrict__ G,
                                                  const float* __restrict__ RSC,
                                                  const float* __restrict__ W,
                                                  const float* __restrict__ b) {
    extern __shared__ float sm[];
    float*  Gt  = sm;                              // Gt[k*GT_STRIDE + r]
    float2* Wt2 = (float2*)(sm + 64 * GT_STRIDE);  // Wt2[k*64 + c] = {W[c][k], W[c][k]}
    __shared__ float bs[64];

    const int tid  = threadIdx.x;
    const int row0 = blockIdx.x * 256;

    // W duplicated into smem (4096 elems / 128 thr)
    #pragma unroll
    for (int idx = tid; idx < 64 * 64; idx += 128) {
        int c = idx >> 6, k = idx & 63;
        float w = W[idx];
        Wt2[k * 64 + c] = make_float2(w, w);
    }
    if (tid < 64) bs[tid] = b[tid];

    // Input tile transposed: Gt[k][r]
    for (int idx = tid; idx < 256 * 64; idx += 128) {
        int r = idx >> 6, k = idx & 63;
        int row = row0 + r;
        float v = 0.0f;
        if (row < N_NODES)           v = G[row * CIN + k];
        else if (row < 2 * N_NODES)  v = RSC[(row - N_NODES) * CIN + k];
        Gt[k * GT_STRIDE + r] = v;
    }
    __syncthreads();

    const int r0 = (tid & 15) * 16;   // 16 rows  (8 packed pairs)
    const int c0 = (tid >> 4) * 8;    // 8 cols

    unsigned long long acc[8][8];
    #pragma unroll
    for (int i = 0; i < 8; i++)
        #pragma unroll
        for (int j = 0; j < 8; j++) acc[i][j] = 0ull;   // {0.f, 0.f}

    #pragma unroll 4
    for (int k = 0; k < 64; k++) {
        const ulonglong2* rp = (const ulonglong2*)&Gt[k * GT_STRIDE + r0];
        ulonglong2 ra = rp[0], rb = rp[1], rc = rp[2], rd = rp[3];
        const ulonglong2* cp = (const ulonglong2*)&Wt2[k * 64 + c0];
        ulonglong2 ca = cp[0], cb = cp[1], cc = cp[2], cd = cp[3];

        unsigned long long rr[8] = {ra.x, ra.y, rb.x, rb.y, rc.x, rc.y, rd.x, rd.y};
        unsigned long long cc_[8] = {ca.x, ca.y, cb.x, cb.y, cc.x, cc.y, cd.x, cd.y};

        #pragma unroll
        for (int i = 0; i < 8; i++)
            #pragma unroll
            for (int j = 0; j < 8; j++)
                FMA2(acc[i][j], rr[i], cc_[j], acc[i][j]);
    }

    const float4 bb0 = *(const float4*)&bs[c0];
    const float4 bb1 = *(const float4*)&bs[c0 + 4];

    #pragma unroll
    for (int i = 0; i < 8; i++) {
        float2 f[8];
        #pragma unroll
        for (int j = 0; j < 8; j++) f[j] = *(float2*)&acc[i][j];

        // pair i holds rows (r0+2i, r0+2i+1): .x = even row, .y = odd row
        #pragma unroll
        for (int h = 0; h < 2; h++) {
            int row = row0 + r0 + 2 * i + h;
            float4 vA, vB;
            if (h == 0) { vA = make_float4(f[0].x, f[1].x, f[2].x, f[3].x);
                          vB = make_float4(f[4].x, f[5].x, f[6].x, f[7].x); }
            else        { vA = make_float4(f[0].y, f[1].y, f[2].y, f[3].y);
                          vB = make_float4(f[4].y, f[5].y, f[6].y, f[7].y); }
            if (row < N_NODES) {
                *(float4*)&d_GW[row * COUT + c0]     = vA;
                *(float4*)&d_GW[row * COUT + c0 + 4] = vB;
            } else if (row < 2 * N_NODES) {
                vA.x -= bb0.x; vA.y -= bb0.y; vA.z -= bb0.z; vA.w -= bb0.w;
                vB.x -= bb1.x; vB.y -= bb1.y; vB.z -= bb1.z; vB.w -= bb1.w;
                int rr2 = row - N_NODES;
                *(float4*)&d_RWb[rr2 * COUT + c0]     = vA;
                *(float4*)&d_RWb[rr2 * COUT + c0 + 4] = vB;
            }
        }
    }
}

// =====================================================================
// K2: histogram of dst (int32 — JAX x64 disabled downcasts the int64 request)
// 4 edges per thread via int4.
// =====================================================================
__global__ void k2_hist(const int* __restrict__ dst, int E) {
    int e = (blockIdx.x * blockDim.x + threadIdx.x) * 4;
    if (e + 3 < E) {
        int4 d4 = *(const int4*)(dst + e);
        if ((unsigned)d4.x < N_NODES) atomicAdd(&d_deg[d4.x], 1);
        if ((unsigned)d4.y < N_NODES) atomicAdd(&d_deg[d4.y], 1);
        if ((unsigned)d4.z < N_NODES) atomicAdd(&d_deg[d4.z], 1);
        if ((unsigned)d4.w < N_NODES) atomicAdd(&d_deg[d4.w], 1);
    } else {
        for (; e < E; e++) {
            unsigned d = (unsigned)dst[e];
            if (d < N_NODES) atomicAdd(&d_deg[d], 1);
        }
    }
}

// =====================================================================
// K3: distributed region allocation: per-block scan + one atomicAdd on
// the global allocator (d_deg[N_NODES]). Region order irrelevant.
// =====================================================================
__global__ __launch_bounds__(1024) void k3_scan() {
    const int t = threadIdx.x;
    const int i = blockIdx.x * 1024 + t;
    const int lane = t & 31;
    const int wid  = t >> 5;

    int v = (i < N_NODES) ? d_deg[i] : 0;

    int x = v;
    #pragma unroll
    for (int o = 1; o < 32; o <<= 1) {
        int y = __shfl_up_sync(0xffffffffu, x, o);
        if (lane >= o) x += y;
    }

    __shared__ int wsum[32];
    __shared__ int base;
    if (lane == 31) wsum[wid] = x;
    __syncthreads();

    if (wid == 0) {
        int y = wsum[lane];
        #pragma unroll
        for (int o = 1; o < 32; o <<= 1) {
            int z = __shfl_up_sync(0xffffffffu, y, o);
            if (lane >= o) y += z;
        }
        wsum[lane] = y;
        if (lane == 31) base = atomicAdd(&d_deg[N_NODES], y);
    }
    __syncthreads();

    int incl = x + ((wid > 0) ? wsum[wid - 1] : 0);
    if (i < N_NODES) d_cursor[i] = base + incl - v;
}

// =====================================================================
// K4: scatter edges into CSR buckets (4 edges per thread)
// =====================================================================
__device__ __forceinline__ void scat1(int s, int d) {
    if ((unsigned)d < N_NODES) {
        int p = atomicAdd(&d_cursor[d], 1);
        d_esrc[p] = ((unsigned)s < N_NODES) ? s : 0;
    }
}

__global__ void k4_scatter(const int* __restrict__ src,
                           const int* __restrict__ dst, int E) {
    int e = (blockIdx.x * blockDim.x + threadIdx.x) * 4;
    if (e + 3 < E) {
        int4 s4 = *(const int4*)(src + e);
        int4 d4 = *(const int4*)(dst + e);
        scat1(s4.x, d4.x);
        scat1(s4.y, d4.y);
        scat1(s4.z, d4.z);
        scat1(s4.w, d4.w);
    } else {
        for (; e < E; e++) scat1(src[e], dst[e]);
    }
}

// =====================================================================
// K5: per-node aggregation. One warp per node; each lane owns 2 channels.
// =====================================================================
__global__ __launch_bounds__(256) void k5_agg(float* __restrict__ out) {
    const int warp = (blockIdx.x * blockDim.x + threadIdx.x) >> 5;
    if (warp >= N_NODES) return;
    const int lane = threadIdx.x & 31;
    const int node = warp;

    const int end = d_cursor[node];     // after scatter: start + deg
    const int deg = d_deg[node];
    const int start = end - deg;

    const float2 c = *reinterpret_cast<const float2*>(&d_RWb[node * COUT + 2 * lane]);

    float mx0 = 0.f, mx1 = 0.f, s0 = 0.f, s1 = 0.f;

    int i = start;
    for (; i + 3 < end; i += 4) {
        int a = d_esrc[i], b_ = d_esrc[i+1], cidx = d_esrc[i+2], d = d_esrc[i+3];
        float2 g0 = *reinterpret_cast<const float2*>(&d_GW[a    * COUT + 2 * lane]);
        float2 g1 = *reinterpret_cast<const float2*>(&d_GW[b_   * COUT + 2 * lane]);
        float2 g2 = *reinterpret_cast<const float2*>(&d_GW[cidx * COUT + 2 * lane]);
        float2 g3 = *reinterpret_cast<const float2*>(&d_GW[d    * COUT + 2 * lane]);
        float v;
        v = fmaxf(g0.x - c.x, 0.f); mx0 = fmaxf(mx0, v); s0 += v;
        v = fmaxf(g0.y - c.y, 0.f); mx1 = fmaxf(mx1, v); s1 += v;
        v = fmaxf(g1.x - c.x, 0.f); mx0 = fmaxf(mx0, v); s0 += v;
        v = fmaxf(g1.y - c.y, 0.f); mx1 = fmaxf(mx1, v); s1 += v;
        v = fmaxf(g2.x - c.x, 0.f); mx0 = fmaxf(mx0, v); s0 += v;
        v = fmaxf(g2.y - c.y, 0.f); mx1 = fmaxf(mx1, v); s1 += v;
        v = fmaxf(g3.x - c.x, 0.f); mx0 = fmaxf(mx0, v); s0 += v;
        v = fmaxf(g3.y - c.y, 0.f); mx1 = fmaxf(mx1, v); s1 += v;
    }
    for (; i < end; i++) {
        int a = d_esrc[i];
        float2 g = *reinterpret_cast<const float2*>(&d_GW[a * COUT + 2 * lane]);
        float v;
        v = fmaxf(g.x - c.x, 0.f); mx0 = fmaxf(mx0, v); s0 += v;
        v = fmaxf(g.y - c.y, 0.f); mx1 = fmaxf(mx1, v); s1 += v;
    }

    const float inv = 1.0f / (float)((deg > 0) ? deg : 1);
    out[node * 128 + 2 * lane]          = mx0;
    out[node * 128 + 2 * lane + 1]      = mx1;
    out[node * 128 + 64 + 2 * lane]     = s0 * inv;
    out[node * 128 + 64 + 2 * lane + 1] = s1 * inv;
}

// =====================================================================
// launch
// =====================================================================
extern "C" void kernel_launch(void* const* d_in, const int* in_sizes, int n_in,
                              void* d_out, int out_size) {
    const float* G   = (const float*)d_in[0];
    const float* RSC = (const float*)d_in[1];
    const int*   src = (const int*)d_in[2];
    const int*   dst = (const int*)d_in[3];
    const float* W   = (const float*)d_in[4];
    const float* b   = (const float*)d_in[5];
    float* out = (float*)d_out;

    int E = in_sizes[2];
    if (E > E_MAX) E = E_MAX;

    // zero histogram + allocator in one async memset (capturable)
    void* degp = nullptr;
    cudaGetSymbolAddress(&degp, d_deg);
    cudaMemsetAsync(degp, 0, (N_NODES + 1) * sizeof(int), 0);

    cudaFuncSetAttribute(k1_gemm, cudaFuncAttributeMaxDynamicSharedMemorySize,
                         SMEM_K1_BYTES);
    k1_gemm<<<(2 * N_NODES + 255) / 256, 128, SMEM_K1_BYTES>>>(G, RSC, W, b);

    k2_hist<<<(E / 4 + 255) / 256, 256>>>(dst, E);
    k3_scan<<<(N_NODES + 1023) / 1024, 1024>>>();
    k4_scatter<<<(E / 4 + 255) / 256, 256>>>(src, dst, E);
    k5_agg<<<(N_NODES * 32 + 255) / 256, 256>>>(out);
}